// round 10
// baseline (speedup 1.0000x reference)
#include <cuda_runtime.h>
#include <math.h>

#define BB 8
#define NLEN 512
#define CDIM 128
#define NNE (NLEN*NLEN)          // 262144 = 2^18
#define KSEL 43690               // NNE//6
#define FSCALE 0.08838834764831845f
#define CAP 4096

typedef unsigned long long u64;

#define FMA2(d, a, b, c) \
    asm("fma.rn.f32x2 %0, %1, %2, %3;" : "=l"(d) : "l"(a), "l"(b), "l"(c))
#define PACK2(d, x) \
    asm("mov.b64 %0, {%1, %1};" : "=l"(d) : "f"(x))
#define UNPACK2(lo, hi, v) \
    asm("mov.b64 {%0, %1}, %2;" : "=f"(lo), "=f"(hi) : "l"(v))

// ---------------- scratch (static device globals; no allocation) -------------
static __device__ float g_E [BB*NNE];
static __device__ float g_Ch[BB*NNE];
static __device__ float g_V [BB*NNE];
static __device__ float g_L [BB*NNE];   // logits, then attn after softmax
static __device__ float g_W [BB*NNE];
static __device__ float g_sq[BB*NLEN];
static __device__ float g_mu[BB*NLEN];
static __device__ float g_ds[BB*NLEN];
static __device__ unsigned int g_hist[3*BB*256];
static __device__ unsigned int g_cnt[BB];
static __device__ unsigned long long g_cand[BB*CAP];
static __device__ unsigned long long g_cut[BB];

__device__ __forceinline__ unsigned int ford(float f) {
    unsigned int u = __float_as_uint(f);
    return (u & 0x80000000u) ? ~u : (u | 0x80000000u);   // monotone float->uint
}

// ------- per-row stats (+ fused zeroing of hist/cnt state) ------------------
__global__ void stats_kernel(const float* __restrict__ x) {
    int z = blockIdx.x * 256 + threadIdx.x;
    if (z < 3*BB*256) g_hist[z] = 0u;
    if (z < BB)       g_cnt[z]  = 0u;

    int row  = blockIdx.x * 8 + (threadIdx.x >> 5);     // 4096 rows
    int lane = threadIdx.x & 31;
    const float* xr = x + (size_t)row * CDIM;
    float v[4]; float s = 0.f, ss = 0.f;
#pragma unroll
    for (int i = 0; i < 4; i++) {
        v[i] = xr[lane + 32*i];
        s  += v[i];
        ss += v[i]*v[i];
    }
#pragma unroll
    for (int o = 16; o; o >>= 1) {
        s  += __shfl_xor_sync(0xffffffffu, s,  o);
        ss += __shfl_xor_sync(0xffffffffu, ss, o);
    }
    float mu = s * (1.0f/CDIM);
    float cs = 0.f;
#pragma unroll
    for (int i = 0; i < 4; i++) { float d = v[i]-mu; cs += d*d; }
#pragma unroll
    for (int o = 16; o; o >>= 1) cs += __shfl_xor_sync(0xffffffffu, cs, o);
    if (lane == 0) { g_mu[row] = mu; g_sq[row] = ss; g_ds[row] = sqrtf(cs); }
}

// ---------------- E / Ch / V tiles: symmetric, upper-triangle blocks --------
// 512 threads, 2x4 micro-tile, FMA2 gram (bitwise == scalar fmaf chain).
__global__ void __launch_bounds__(512) ecv_kernel(const float* __restrict__ x) {
    __shared__ __align__(16) float Xn[64][68];
    __shared__ __align__(16) float Xm[64][68];
    int b  = blockIdx.y;
    int r = blockIdx.x, bi = 0;
    while (r >= 8 - bi) { r -= 8 - bi; bi++; }
    int bj = bi + r;
    int i0 = bi * 64, j0 = bj * 64;
    int t  = threadIdx.x;
    int tx = t & 15, ty = t >> 4;       // tx: col-quad 0..15, ty: row-pair 0..31
    const float* xb = x + (size_t)b * NLEN * CDIM;

    u64 g2[2][2];
    u64 zero2; { float z = 0.f; PACK2(zero2, z); }
    g2[0][0]=zero2; g2[0][1]=zero2; g2[1][0]=zero2; g2[1][1]=zero2;
    float ch[2][4];
#pragma unroll
    for (int i = 0; i < 2; i++)
#pragma unroll
        for (int j = 0; j < 4; j++) ch[i][j] = 0.f;

    for (int ph = 0; ph < 2; ph++) {
        int cbase = ph * 64;
#pragma unroll
        for (int it = 0; it < 2; it++) {
            int idx = t + 512*it;            // 0..1023 float4 slots
            int rr  = idx >> 4;              // 0..63
            int c4  = (idx & 15) * 4;        // 0..60
            float4 a = *(const float4*)&xb[(size_t)(i0+rr)*CDIM + cbase + c4];
            Xn[c4+0][rr] = a.x; Xn[c4+1][rr] = a.y; Xn[c4+2][rr] = a.z; Xn[c4+3][rr] = a.w;
            float4 m = *(const float4*)&xb[(size_t)(j0+rr)*CDIM + cbase + c4];
            Xm[c4+0][rr] = m.x; Xm[c4+1][rr] = m.y; Xm[c4+2][rr] = m.z; Xm[c4+3][rr] = m.w;
        }
        __syncthreads();
#pragma unroll 4
        for (int c = 0; c < 64; c++) {
            float2 a2 = *(const float2*)&Xn[c][ty*2];
            ulonglong2 bp = *(const ulonglong2*)&Xm[c][tx*4];
            float b0, b1, b2, b3;
            UNPACK2(b0, b1, bp.x);
            UNPACK2(b2, b3, bp.y);
            u64 ax, ay;
            PACK2(ax, a2.x); PACK2(ay, a2.y);
            FMA2(g2[0][0], ax, bp.x, g2[0][0]);
            FMA2(g2[0][1], ax, bp.y, g2[0][1]);
            FMA2(g2[1][0], ay, bp.x, g2[1][0]);
            FMA2(g2[1][1], ay, bp.y, g2[1][1]);
            ch[0][0] = fmaxf(ch[0][0], fabsf(a2.x - b0));
            ch[0][1] = fmaxf(ch[0][1], fabsf(a2.x - b1));
            ch[0][2] = fmaxf(ch[0][2], fabsf(a2.x - b2));
            ch[0][3] = fmaxf(ch[0][3], fabsf(a2.x - b3));
            ch[1][0] = fmaxf(ch[1][0], fabsf(a2.y - b0));
            ch[1][1] = fmaxf(ch[1][1], fabsf(a2.y - b1));
            ch[1][2] = fmaxf(ch[1][2], fabsf(a2.y - b2));
            ch[1][3] = fmaxf(ch[1][3], fabsf(a2.y - b3));
        }
        __syncthreads();
    }

    float g[2][4];
    UNPACK2(g[0][0], g[0][1], g2[0][0]);
    UNPACK2(g[0][2], g[0][3], g2[0][1]);
    UNPACK2(g[1][0], g[1][1], g2[1][0]);
    UNPACK2(g[1][2], g[1][3], g2[1][1]);

    int ib = b*NLEN + i0 + ty*2;
    int jb = b*NLEN + j0 + tx*4;
    float sqi[2], mui[2], dsi[2], sqj[4], muj[4], dsj[4];
#pragma unroll
    for (int q = 0; q < 2; q++) {
        sqi[q] = g_sq[ib+q]; mui[q] = g_mu[ib+q]; dsi[q] = g_ds[ib+q];
    }
#pragma unroll
    for (int q = 0; q < 4; q++) {
        sqj[q] = g_sq[jb+q]; muj[q] = g_mu[jb+q]; dsj[q] = g_ds[jb+q];
    }
    float e[2][4], v[2][4];
#pragma unroll
    for (int i = 0; i < 2; i++)
#pragma unroll
        for (int j = 0; j < 4; j++) {
            float d2 = sqi[i] + sqj[j] - 2.0f * g[i][j];
            e[i][j] = sqrtf(fmaxf(d2, 0.0f));
            float cov = g[i][j] - (float)CDIM * mui[i] * muj[j];
            float vv  = cov / (dsi[i] * dsj[j]);
            v[i][j] = fminf(fmaxf(vv, -1.0f), 1.0f);
        }
#pragma unroll
    for (int i = 0; i < 2; i++) {
        size_t off = (size_t)b*NNE + (size_t)(i0 + ty*2 + i)*NLEN + j0 + tx*4;
        *(float4*)&g_E [off] = make_float4(e[i][0], e[i][1], e[i][2], e[i][3]);
        *(float4*)&g_Ch[off] = make_float4(ch[i][0], ch[i][1], ch[i][2], ch[i][3]);
        *(float4*)&g_V [off] = make_float4(v[i][0], v[i][1], v[i][2], v[i][3]);
    }
    if (bi != bj) {
        size_t mbase = (size_t)b*NNE;
#pragma unroll
        for (int j = 0; j < 4; j++) {
            size_t rowoff = mbase + (size_t)(j0 + tx*4 + j)*NLEN + i0 + ty*2;
            float2 me = make_float2(e[0][j], e[1][j]);
            float2 mc = make_float2(ch[0][j], ch[1][j]);
            float2 mv = make_float2(v[0][j], v[1][j]);
            *(float2*)&g_E [rowoff] = me;
            *(float2*)&g_Ch[rowoff] = mc;
            *(float2*)&g_V [rowoff] = mv;
        }
    }
}

// ------- 128x128x8 double-buffered fp32 GEMM, 512 threads, FFMA2 ------------
// Full K=512, sequential accumulation per output (bitwise == scalar fmaf chain)
// Micro-tile 4x8 per thread; same conflict-free tx*4 / tx*4+64 column layout
// and identical 16:3 FMA2:LDS issue ratio as the proven 256-thread body.
// TRANSB=true : C[n,m] = sum_k A[n,k] * B[m,k]  (NT)
// TRANSB=false: C[n,k] = sum_m A[n,m] * B[m,k]  (NN)
// HIST: fuse radix pass-0 histogram of ford(C)>>24 into the epilogue.
template<bool TRANSB, bool HIST>
__device__ __forceinline__ void gemm128_512_body(const float* __restrict__ A,
                                                 const float* __restrict__ B,
                                                 float* __restrict__ C, int batch) {
    __shared__ __align__(16) float As[2][8][132];
    __shared__ __align__(16) float Bs[2][8][132];
    __shared__ unsigned hist[HIST ? 256 : 1];
    int i0 = blockIdx.y * 128, j0 = blockIdx.x * 128;
    int t  = threadIdx.x;                    // 0..511
    int tx = t & 15, ty = t >> 4;            // tx 0..15, ty 0..31
    bool isA = t < 256;
    int lt = t & 255;
    int lr = lt >> 1, lc = (lt & 1) * 4;     // A / NT-B: row 0..127, k-offset
    int bk = lt >> 5, bc = (lt & 31) * 4;    // NN-B: k-row 0..7, col-offset

    if (HIST && t < 256) hist[t] = 0u;

    // packed accumulators: acc2[i][jp]; i: row ty*4+i, jp: col pair
    // cols: jp<2 -> tx*4 + 2*jp{,+1}; jp>=2 -> 64 + tx*4 + 2*(jp-2){,+1}
    u64 acc2[4][4];
    u64 zero2; { float z = 0.f; PACK2(zero2, z); }
#pragma unroll
    for (int i = 0; i < 4; i++)
#pragma unroll
        for (int j = 0; j < 4; j++) acc2[i][j] = zero2;

    float4 pv;
    // prologue: k-tile 0 (threads 0-255 load A, 256-511 load B)
    if (isA) pv = *(const float4*)&A[(size_t)(i0+lr)*NLEN + lc];
    else if (TRANSB) pv = *(const float4*)&B[(size_t)(j0+lr)*NLEN + lc];
    else             pv = *(const float4*)&B[(size_t)bk*NLEN + j0 + bc];
    if (isA) {
        As[0][lc+0][lr]=pv.x; As[0][lc+1][lr]=pv.y; As[0][lc+2][lr]=pv.z; As[0][lc+3][lr]=pv.w;
    } else if (TRANSB) {
        Bs[0][lc+0][lr]=pv.x; Bs[0][lc+1][lr]=pv.y; Bs[0][lc+2][lr]=pv.z; Bs[0][lc+3][lr]=pv.w;
    } else {
        *(float4*)&Bs[0][bk][bc] = pv;
    }
    __syncthreads();

    int cur = 0;
    for (int kb = 0; kb < NLEN; kb += 8) {
        bool notlast = (kb + 8 < NLEN);
        if (notlast) {
            if (isA) pv = *(const float4*)&A[(size_t)(i0+lr)*NLEN + kb + 8 + lc];
            else if (TRANSB) pv = *(const float4*)&B[(size_t)(j0+lr)*NLEN + kb + 8 + lc];
            else             pv = *(const float4*)&B[(size_t)(kb+8+bk)*NLEN + j0 + bc];
        }
#pragma unroll
        for (int kk = 0; kk < 8; kk++) {
            float a[4];
            *(float4*)&a[0] = *(const float4*)&As[cur][kk][ty*4];
            ulonglong2 blo = *(const ulonglong2*)&Bs[cur][kk][tx*4];
            ulonglong2 bhi = *(const ulonglong2*)&Bs[cur][kk][tx*4 + 64];
#pragma unroll
            for (int i = 0; i < 4; i++) {
                u64 aa; PACK2(aa, a[i]);
                FMA2(acc2[i][0], aa, blo.x, acc2[i][0]);
                FMA2(acc2[i][1], aa, blo.y, acc2[i][1]);
                FMA2(acc2[i][2], aa, bhi.x, acc2[i][2]);
                FMA2(acc2[i][3], aa, bhi.y, acc2[i][3]);
            }
        }
        if (notlast) {
            int nb = cur ^ 1;
            if (isA) {
                As[nb][lc+0][lr]=pv.x; As[nb][lc+1][lr]=pv.y; As[nb][lc+2][lr]=pv.z; As[nb][lc+3][lr]=pv.w;
            } else if (TRANSB) {
                Bs[nb][lc+0][lr]=pv.x; Bs[nb][lc+1][lr]=pv.y; Bs[nb][lc+2][lr]=pv.z; Bs[nb][lc+3][lr]=pv.w;
            } else {
                *(float4*)&Bs[nb][bk][bc] = pv;
            }
            __syncthreads();
            cur = nb;
        }
    }
#pragma unroll
    for (int i = 0; i < 4; i++) {
        int row = i0 + ty*4 + i;
#pragma unroll
        for (int gj = 0; gj < 2; gj++) {
            float4 rv;
            UNPACK2(rv.x, rv.y, acc2[i][gj*2+0]);
            UNPACK2(rv.z, rv.w, acc2[i][gj*2+1]);
            *(float4*)&C[(size_t)row*NLEN + j0 + gj*64 + tx*4] = rv;
            if (HIST) {
                atomicAdd(&hist[ford(rv.x) >> 24], 1u);
                atomicAdd(&hist[ford(rv.y) >> 24], 1u);
                atomicAdd(&hist[ford(rv.z) >> 24], 1u);
                atomicAdd(&hist[ford(rv.w) >> 24], 1u);
            }
        }
    }
    if (HIST) {
        __syncthreads();
        if (t < 256 && hist[t]) atomicAdd(&g_hist[0*BB*256 + batch*256 + t], hist[t]);
    }
}

__global__ void __launch_bounds__(512) gemm_nt_kernel() {
    size_t o = (size_t)blockIdx.z * NNE;
    gemm128_512_body<true, false>(g_E + o, g_Ch + o, g_L + o, blockIdx.z);
}

__global__ void __launch_bounds__(512) gemm_nn_kernel() {
    size_t o = (size_t)blockIdx.z * NNE;
    gemm128_512_body<false, true>(g_L + o, g_V + o, g_W + o, blockIdx.z);
}

// ---------------- row softmax of L*SCALE (in place) -------------------------
__global__ void softmax_kernel() {
    __shared__ float red[128];
    int row = blockIdx.x;                          // 0..4095
    float* p = g_L + (size_t)row * NLEN;
    int t = threadIdx.x;
    float v[4]; float mx = -3.4e38f;
#pragma unroll
    for (int q = 0; q < 4; q++) { v[q] = p[t + 128*q] * FSCALE; mx = fmaxf(mx, v[q]); }
    red[t] = mx; __syncthreads();
    for (int o = 64; o; o >>= 1) { if (t < o) red[t] = fmaxf(red[t], red[t+o]); __syncthreads(); }
    mx = red[0]; __syncthreads();
    float e[4]; float s = 0.f;
#pragma unroll
    for (int q = 0; q < 4; q++) { e[q] = expf(v[q] - mx); s += e[q]; }
    red[t] = s; __syncthreads();
    for (int o = 64; o; o >>= 1) { if (t < o) red[t] += red[t+o]; __syncthreads(); }
    s = red[0];
#pragma unroll
    for (int q = 0; q < 4; q++) p[t + 128*q] = e[q] / s;
}

// ---------------- selection: radix passes; prefix recomputed in-block -------
__device__ void compute_sel(int b, int npass, unsigned* sh,
                            unsigned& hi_out, unsigned& need_out) {
    int t = threadIdx.x;
    unsigned hi = 0u, need = (unsigned)KSEL;
    for (int p = 0; p < npass; p++) {
        sh[t] = g_hist[p*BB*256 + b*256 + t];
        __syncthreads();
        for (int off = 1; off < 256; off <<= 1) {
            unsigned add = (t + off < 256) ? sh[t + off] : 0u;
            __syncthreads();
            sh[t] += add;
            __syncthreads();
        }
        unsigned S     = sh[t];
        unsigned Snext = (t < 255) ? sh[t + 1] : 0u;
        __syncthreads();
        if (S >= need && Snext < need) { sh[256] = (unsigned)t; sh[257] = need - Snext; }
        __syncthreads();
        hi   = (hi << 8) | sh[256];
        need = sh[257];
        __syncthreads();
    }
    hi_out = hi; need_out = need;
}

__global__ void hist2_kernel() {
    __shared__ unsigned sh[258];
    int b = blockIdx.y;
    unsigned hi, need;
    compute_sel(b, 1, sh, hi, need);              // 8-bit prefix
    int base = b*NNE + blockIdx.x * (NNE/64);
    for (int i = threadIdx.x; i < NNE/64; i += 256) {
        unsigned int k = ford(g_W[base + i]);
        if ((k >> 24) == hi) atomicAdd(&g_hist[1*BB*256 + b*256 + ((k >> 16) & 255u)], 1u);
    }
}

__global__ void hist3_kernel() {
    __shared__ unsigned sh[258];
    int b = blockIdx.y;
    unsigned hi, need;
    compute_sel(b, 2, sh, hi, need);              // 16-bit prefix
    int base = b*NNE + blockIdx.x * (NNE/64);
    for (int i = threadIdx.x; i < NNE/64; i += 256) {
        unsigned int k = ford(g_W[base + i]);
        if ((k >> 16) == hi) atomicAdd(&g_hist[2*BB*256 + b*256 + ((k >> 8) & 255u)], 1u);
    }
}

__global__ void collect_kernel() {
    __shared__ unsigned sh[258];
    int b = blockIdx.y;
    unsigned hi, need;
    compute_sel(b, 3, sh, hi, need);              // 24-bit prefix
    int base = blockIdx.x * (NNE/64);
    for (int i = threadIdx.x; i < NNE/64; i += 256) {
        int idx = base + i;
        unsigned int k = ford(g_W[b*NNE + idx]);
        if ((k >> 8) == hi) {
            unsigned int pos = atomicAdd(&g_cnt[b], 1u);
            if (pos < CAP)
                g_cand[b*CAP + pos] = ((unsigned long long)k << 32) | (unsigned int)idx;
        }
    }
}

__global__ void select_kernel() {
    __shared__ unsigned long long s[CAP];
    __shared__ unsigned sh[258];
    int b = blockIdx.x, t = threadIdx.x;
    unsigned hi, need;
    compute_sel(b, 3, sh, hi, need);
    unsigned int cnt = g_cnt[b]; if (cnt > CAP) cnt = CAP;
    for (unsigned int i = t; i < cnt; i += 256) s[i] = g_cand[b*CAP + i];
    __syncthreads();
    for (unsigned int i = t; i < cnt; i += 256) {
        unsigned long long k = s[i];
        unsigned int greater = 0;
        for (unsigned int j = 0; j < cnt; j++) greater += (s[j] > k);
        if (greater == need - 1) g_cut[b] = k;   // keys unique: exactly one hit
    }
}

__global__ void mask_kernel(float* __restrict__ out) {
    int i = blockIdx.x * blockDim.x + threadIdx.x;
    if (i >= BB*NNE) return;
    int b = i >> 18;                           // NNE = 2^18
    unsigned long long key =
        ((unsigned long long)ford(g_W[i]) << 32) | (unsigned int)(i & (NNE - 1));
    out[i] = (key >= g_cut[b]) ? 1.0f : 0.0f;
}

// ---------------- launch ----------------------------------------------------
extern "C" void kernel_launch(void* const* d_in, const int* in_sizes, int n_in,
                              void* d_out, int out_size) {
    const float* x = (const float*)d_in[0];
    float* out = (float*)d_out;
    (void)in_sizes; (void)n_in; (void)out_size;

    stats_kernel<<<BB*NLEN/8, 256>>>(x);
    ecv_kernel<<<dim3(36, BB), 512>>>(x);
    gemm_nt_kernel<<<dim3(4, 4, BB), 512>>>();
    softmax_kernel<<<BB*NLEN, 128>>>();
    gemm_nn_kernel<<<dim3(4, 4, BB), 512>>>();
    hist2_kernel<<<dim3(64, BB), 256>>>();
    hist3_kernel<<<dim3(64, BB), 256>>>();
    collect_kernel<<<dim3(64, BB), 256>>>();
    select_kernel<<<BB, 256>>>();
    mask_kernel<<<(BB*NNE + 255)/256, 256>>>(out);
}

// round 11
// speedup vs baseline: 1.1102x; 1.1102x over previous
#include <cuda_runtime.h>
#include <math.h>

#define BB 8
#define NLEN 512
#define CDIM 128
#define NNE (NLEN*NLEN)          // 262144 = 2^18
#define KSEL 43690               // NNE//6
#define FSCALE 0.08838834764831845f
#define CAP 4096

typedef unsigned long long u64;

#define FMA2(d, a, b, c) \
    asm("fma.rn.f32x2 %0, %1, %2, %3;" : "=l"(d) : "l"(a), "l"(b), "l"(c))
#define PACK2(d, x) \
    asm("mov.b64 %0, {%1, %1};" : "=l"(d) : "f"(x))
#define UNPACK2(lo, hi, v) \
    asm("mov.b64 {%0, %1}, %2;" : "=f"(lo), "=f"(hi) : "l"(v))

// ---------------- scratch (static device globals; no allocation) -------------
static __device__ float g_E [BB*NNE];
static __device__ float g_Ch[BB*NNE];
static __device__ float g_V [BB*NNE];
static __device__ float g_L [BB*NNE];   // logits, then attn after softmax
static __device__ float g_W [BB*NNE];
static __device__ float g_sq[BB*NLEN];
static __device__ float g_mu[BB*NLEN];
static __device__ float g_ds[BB*NLEN];
static __device__ unsigned int g_hist[3*BB*256];
static __device__ unsigned int g_cnt[BB];
static __device__ unsigned long long g_cand[BB*CAP];
static __device__ unsigned long long g_cut[BB];

__device__ __forceinline__ unsigned int ford(float f) {
    unsigned int u = __float_as_uint(f);
    return (u & 0x80000000u) ? ~u : (u | 0x80000000u);   // monotone float->uint
}

// ------- per-row stats (+ fused zeroing of hist/cnt state) ------------------
__global__ void stats_kernel(const float* __restrict__ x) {
    int z = blockIdx.x * 256 + threadIdx.x;
    if (z < 3*BB*256) g_hist[z] = 0u;
    if (z < BB)       g_cnt[z]  = 0u;

    int row  = blockIdx.x * 8 + (threadIdx.x >> 5);     // 4096 rows
    int lane = threadIdx.x & 31;
    const float* xr = x + (size_t)row * CDIM;
    float v[4]; float s = 0.f, ss = 0.f;
#pragma unroll
    for (int i = 0; i < 4; i++) {
        v[i] = xr[lane + 32*i];
        s  += v[i];
        ss += v[i]*v[i];
    }
#pragma unroll
    for (int o = 16; o; o >>= 1) {
        s  += __shfl_xor_sync(0xffffffffu, s,  o);
        ss += __shfl_xor_sync(0xffffffffu, ss, o);
    }
    float mu = s * (1.0f/CDIM);
    float cs = 0.f;
#pragma unroll
    for (int i = 0; i < 4; i++) { float d = v[i]-mu; cs += d*d; }
#pragma unroll
    for (int o = 16; o; o >>= 1) cs += __shfl_xor_sync(0xffffffffu, cs, o);
    if (lane == 0) { g_mu[row] = mu; g_sq[row] = ss; g_ds[row] = sqrtf(cs); }
}

// ---------------- E / Ch / V tiles: symmetric, upper-triangle blocks --------
// 512 threads, 2x4 micro-tile, FMA2 gram (bitwise == scalar fmaf chain).
__global__ void __launch_bounds__(512) ecv_kernel(const float* __restrict__ x) {
    __shared__ __align__(16) float Xn[64][68];
    __shared__ __align__(16) float Xm[64][68];
    int b  = blockIdx.y;
    int r = blockIdx.x, bi = 0;
    while (r >= 8 - bi) { r -= 8 - bi; bi++; }
    int bj = bi + r;
    int i0 = bi * 64, j0 = bj * 64;
    int t  = threadIdx.x;
    int tx = t & 15, ty = t >> 4;       // tx: col-quad 0..15, ty: row-pair 0..31
    const float* xb = x + (size_t)b * NLEN * CDIM;

    u64 g2[2][2];
    u64 zero2; { float z = 0.f; PACK2(zero2, z); }
    g2[0][0]=zero2; g2[0][1]=zero2; g2[1][0]=zero2; g2[1][1]=zero2;
    float ch[2][4];
#pragma unroll
    for (int i = 0; i < 2; i++)
#pragma unroll
        for (int j = 0; j < 4; j++) ch[i][j] = 0.f;

    for (int ph = 0; ph < 2; ph++) {
        int cbase = ph * 64;
#pragma unroll
        for (int it = 0; it < 2; it++) {
            int idx = t + 512*it;            // 0..1023 float4 slots
            int rr  = idx >> 4;              // 0..63
            int c4  = (idx & 15) * 4;        // 0..60
            float4 a = *(const float4*)&xb[(size_t)(i0+rr)*CDIM + cbase + c4];
            Xn[c4+0][rr] = a.x; Xn[c4+1][rr] = a.y; Xn[c4+2][rr] = a.z; Xn[c4+3][rr] = a.w;
            float4 m = *(const float4*)&xb[(size_t)(j0+rr)*CDIM + cbase + c4];
            Xm[c4+0][rr] = m.x; Xm[c4+1][rr] = m.y; Xm[c4+2][rr] = m.z; Xm[c4+3][rr] = m.w;
        }
        __syncthreads();
#pragma unroll 4
        for (int c = 0; c < 64; c++) {
            float2 a2 = *(const float2*)&Xn[c][ty*2];
            ulonglong2 bp = *(const ulonglong2*)&Xm[c][tx*4];
            float b0, b1, b2, b3;
            UNPACK2(b0, b1, bp.x);
            UNPACK2(b2, b3, bp.y);
            u64 ax, ay;
            PACK2(ax, a2.x); PACK2(ay, a2.y);
            FMA2(g2[0][0], ax, bp.x, g2[0][0]);
            FMA2(g2[0][1], ax, bp.y, g2[0][1]);
            FMA2(g2[1][0], ay, bp.x, g2[1][0]);
            FMA2(g2[1][1], ay, bp.y, g2[1][1]);
            ch[0][0] = fmaxf(ch[0][0], fabsf(a2.x - b0));
            ch[0][1] = fmaxf(ch[0][1], fabsf(a2.x - b1));
            ch[0][2] = fmaxf(ch[0][2], fabsf(a2.x - b2));
            ch[0][3] = fmaxf(ch[0][3], fabsf(a2.x - b3));
            ch[1][0] = fmaxf(ch[1][0], fabsf(a2.y - b0));
            ch[1][1] = fmaxf(ch[1][1], fabsf(a2.y - b1));
            ch[1][2] = fmaxf(ch[1][2], fabsf(a2.y - b2));
            ch[1][3] = fmaxf(ch[1][3], fabsf(a2.y - b3));
        }
        __syncthreads();
    }

    float g[2][4];
    UNPACK2(g[0][0], g[0][1], g2[0][0]);
    UNPACK2(g[0][2], g[0][3], g2[0][1]);
    UNPACK2(g[1][0], g[1][1], g2[1][0]);
    UNPACK2(g[1][2], g[1][3], g2[1][1]);

    int ib = b*NLEN + i0 + ty*2;
    int jb = b*NLEN + j0 + tx*4;
    float sqi[2], mui[2], dsi[2], sqj[4], muj[4], dsj[4];
#pragma unroll
    for (int q = 0; q < 2; q++) {
        sqi[q] = g_sq[ib+q]; mui[q] = g_mu[ib+q]; dsi[q] = g_ds[ib+q];
    }
#pragma unroll
    for (int q = 0; q < 4; q++) {
        sqj[q] = g_sq[jb+q]; muj[q] = g_mu[jb+q]; dsj[q] = g_ds[jb+q];
    }
    float e[2][4], v[2][4];
#pragma unroll
    for (int i = 0; i < 2; i++)
#pragma unroll
        for (int j = 0; j < 4; j++) {
            float d2 = sqi[i] + sqj[j] - 2.0f * g[i][j];
            e[i][j] = sqrtf(fmaxf(d2, 0.0f));
            float cov = g[i][j] - (float)CDIM * mui[i] * muj[j];
            float vv  = cov / (dsi[i] * dsj[j]);
            v[i][j] = fminf(fmaxf(vv, -1.0f), 1.0f);
        }
#pragma unroll
    for (int i = 0; i < 2; i++) {
        size_t off = (size_t)b*NNE + (size_t)(i0 + ty*2 + i)*NLEN + j0 + tx*4;
        *(float4*)&g_E [off] = make_float4(e[i][0], e[i][1], e[i][2], e[i][3]);
        *(float4*)&g_Ch[off] = make_float4(ch[i][0], ch[i][1], ch[i][2], ch[i][3]);
        *(float4*)&g_V [off] = make_float4(v[i][0], v[i][1], v[i][2], v[i][3]);
    }
    if (bi != bj) {
        size_t mbase = (size_t)b*NNE;
#pragma unroll
        for (int j = 0; j < 4; j++) {
            size_t rowoff = mbase + (size_t)(j0 + tx*4 + j)*NLEN + i0 + ty*2;
            float2 me = make_float2(e[0][j], e[1][j]);
            float2 mc = make_float2(ch[0][j], ch[1][j]);
            float2 mv = make_float2(v[0][j], v[1][j]);
            *(float2*)&g_E [rowoff] = me;
            *(float2*)&g_Ch[rowoff] = mc;
            *(float2*)&g_V [rowoff] = mv;
        }
    }
}

// ------- 64x128x8 double-buffered fp32 GEMM, 256 threads, FFMA2 -------------
// M-split of the proven 128x128 body: 2 CTAs per SM co-resident.
// B smem access keeps the conflict-free tx*4 / tx*4+64 pattern; A is a
// 2-address broadcast at ty*4. Per-output k-chain identical to scalar fmaf
// sequence => results bitwise identical to the 128x128 body.
// TRANSB=true : C[n,m] = sum_k A[n,k] * B[m,k]  (NT)
// TRANSB=false: C[n,k] = sum_m A[n,m] * B[m,k]  (NN)
// HIST: fuse radix pass-0 histogram of ford(C)>>24 into the epilogue.
template<bool TRANSB, bool HIST>
__device__ __forceinline__ void gemm64_body(const float* __restrict__ A,
                                            const float* __restrict__ B,
                                            float* __restrict__ C, int batch) {
    __shared__ __align__(16) float As[2][8][68];
    __shared__ __align__(16) float Bs[2][8][132];
    __shared__ unsigned hist[HIST ? 256 : 1];
    int i0 = blockIdx.y * 64, j0 = blockIdx.x * 128;
    int t  = threadIdx.x;
    int tx = t & 15, ty = t >> 4;            // tx 0..15, ty 0..15
    int ar = (t & 127) >> 1, ac = (t & 1) * 4;  // A loader: row 0..63 (t<128)
    bool aload = t < 128;
    int br = t >> 1, bq = (t & 1) * 4;       // NT-B loader: row 0..127, k-quad
    int bk = t >> 5, bc = (t & 31) * 4;      // NN-B loader: k-row 0..7, col-off

    if (HIST) hist[t] = 0u;

    // acc2[i][jp]: row ty*4+i; cols jp<2: tx*4+2jp{,+1}; jp>=2: 64+tx*4+2(jp-2){,+1}
    u64 acc2[4][4];
    u64 zero2; { float z = 0.f; PACK2(zero2, z); }
#pragma unroll
    for (int i = 0; i < 4; i++)
#pragma unroll
        for (int j = 0; j < 4; j++) acc2[i][j] = zero2;

    float4 pa, pb;
    if (aload) pa = *(const float4*)&A[(size_t)(i0+ar)*NLEN + ac];
    if (TRANSB) pb = *(const float4*)&B[(size_t)(j0+br)*NLEN + bq];
    else        pb = *(const float4*)&B[(size_t)bk*NLEN + j0 + bc];
    if (aload) { As[0][ac+0][ar]=pa.x; As[0][ac+1][ar]=pa.y; As[0][ac+2][ar]=pa.z; As[0][ac+3][ar]=pa.w; }
    if (TRANSB) { Bs[0][bq+0][br]=pb.x; Bs[0][bq+1][br]=pb.y; Bs[0][bq+2][br]=pb.z; Bs[0][bq+3][br]=pb.w; }
    else        { *(float4*)&Bs[0][bk][bc] = pb; }
    __syncthreads();

    int cur = 0;
    for (int kb = 0; kb < NLEN; kb += 8) {
        bool notlast = (kb + 8 < NLEN);
        if (notlast) {
            if (aload) pa = *(const float4*)&A[(size_t)(i0+ar)*NLEN + kb + 8 + ac];
            if (TRANSB) pb = *(const float4*)&B[(size_t)(j0+br)*NLEN + kb + 8 + bq];
            else        pb = *(const float4*)&B[(size_t)(kb+8+bk)*NLEN + j0 + bc];
        }
#pragma unroll
        for (int kk = 0; kk < 8; kk++) {
            float a[4];
            *(float4*)&a[0] = *(const float4*)&As[cur][kk][ty*4];
            ulonglong2 blo = *(const ulonglong2*)&Bs[cur][kk][tx*4];
            ulonglong2 bhi = *(const ulonglong2*)&Bs[cur][kk][tx*4 + 64];
#pragma unroll
            for (int i = 0; i < 4; i++) {
                u64 aa; PACK2(aa, a[i]);
                FMA2(acc2[i][0], aa, blo.x, acc2[i][0]);
                FMA2(acc2[i][1], aa, blo.y, acc2[i][1]);
                FMA2(acc2[i][2], aa, bhi.x, acc2[i][2]);
                FMA2(acc2[i][3], aa, bhi.y, acc2[i][3]);
            }
        }
        if (notlast) {
            int nb = cur ^ 1;
            if (aload) { As[nb][ac+0][ar]=pa.x; As[nb][ac+1][ar]=pa.y; As[nb][ac+2][ar]=pa.z; As[nb][ac+3][ar]=pa.w; }
            if (TRANSB) { Bs[nb][bq+0][br]=pb.x; Bs[nb][bq+1][br]=pb.y; Bs[nb][bq+2][br]=pb.z; Bs[nb][bq+3][br]=pb.w; }
            else        { *(float4*)&Bs[nb][bk][bc] = pb; }
            __syncthreads();
            cur = nb;
        }
    }
#pragma unroll
    for (int i = 0; i < 4; i++) {
        int row = i0 + ty*4 + i;
#pragma unroll
        for (int gj = 0; gj < 2; gj++) {
            float4 rv;
            UNPACK2(rv.x, rv.y, acc2[i][gj*2+0]);
            UNPACK2(rv.z, rv.w, acc2[i][gj*2+1]);
            *(float4*)&C[(size_t)row*NLEN + j0 + gj*64 + tx*4] = rv;
            if (HIST) {
                atomicAdd(&hist[ford(rv.x) >> 24], 1u);
                atomicAdd(&hist[ford(rv.y) >> 24], 1u);
                atomicAdd(&hist[ford(rv.z) >> 24], 1u);
                atomicAdd(&hist[ford(rv.w) >> 24], 1u);
            }
        }
    }
    if (HIST) {
        __syncthreads();
        if (hist[t]) atomicAdd(&g_hist[0*BB*256 + batch*256 + t], hist[t]);
    }
}

__global__ void __launch_bounds__(256) gemm_nt_kernel() {
    size_t o = (size_t)blockIdx.z * NNE;
    gemm64_body<true, false>(g_E + o, g_Ch + o, g_L + o, blockIdx.z);
}

__global__ void __launch_bounds__(256) gemm_nn_kernel() {
    size_t o = (size_t)blockIdx.z * NNE;
    gemm64_body<false, true>(g_L + o, g_V + o, g_W + o, blockIdx.z);
}

// ---------------- row softmax of L*SCALE (in place) -------------------------
__global__ void softmax_kernel() {
    __shared__ float red[128];
    int row = blockIdx.x;                          // 0..4095
    float* p = g_L + (size_t)row * NLEN;
    int t = threadIdx.x;
    float v[4]; float mx = -3.4e38f;
#pragma unroll
    for (int q = 0; q < 4; q++) { v[q] = p[t + 128*q] * FSCALE; mx = fmaxf(mx, v[q]); }
    red[t] = mx; __syncthreads();
    for (int o = 64; o; o >>= 1) { if (t < o) red[t] = fmaxf(red[t], red[t+o]); __syncthreads(); }
    mx = red[0]; __syncthreads();
    float e[4]; float s = 0.f;
#pragma unroll
    for (int q = 0; q < 4; q++) { e[q] = expf(v[q] - mx); s += e[q]; }
    red[t] = s; __syncthreads();
    for (int o = 64; o; o >>= 1) { if (t < o) red[t] += red[t+o]; __syncthreads(); }
    s = red[0];
#pragma unroll
    for (int q = 0; q < 4; q++) p[t + 128*q] = e[q] / s;
}

// ---------------- selection: radix passes; prefix recomputed in-block -------
__device__ void compute_sel(int b, int npass, unsigned* sh,
                            unsigned& hi_out, unsigned& need_out) {
    int t = threadIdx.x;
    unsigned hi = 0u, need = (unsigned)KSEL;
    for (int p = 0; p < npass; p++) {
        sh[t] = g_hist[p*BB*256 + b*256 + t];
        __syncthreads();
        for (int off = 1; off < 256; off <<= 1) {
            unsigned add = (t + off < 256) ? sh[t + off] : 0u;
            __syncthreads();
            sh[t] += add;
            __syncthreads();
        }
        unsigned S     = sh[t];
        unsigned Snext = (t < 255) ? sh[t + 1] : 0u;
        __syncthreads();
        if (S >= need && Snext < need) { sh[256] = (unsigned)t; sh[257] = need - Snext; }
        __syncthreads();
        hi   = (hi << 8) | sh[256];
        need = sh[257];
        __syncthreads();
    }
    hi_out = hi; need_out = need;
}

__global__ void hist2_kernel() {
    __shared__ unsigned sh[258];
    int b = blockIdx.y;
    unsigned hi, need;
    compute_sel(b, 1, sh, hi, need);              // 8-bit prefix
    int base = b*NNE + blockIdx.x * (NNE/64);
    for (int i = threadIdx.x; i < NNE/64; i += 256) {
        unsigned int k = ford(g_W[base + i]);
        if ((k >> 24) == hi) atomicAdd(&g_hist[1*BB*256 + b*256 + ((k >> 16) & 255u)], 1u);
    }
}

__global__ void hist3_kernel() {
    __shared__ unsigned sh[258];
    int b = blockIdx.y;
    unsigned hi, need;
    compute_sel(b, 2, sh, hi, need);              // 16-bit prefix
    int base = b*NNE + blockIdx.x * (NNE/64);
    for (int i = threadIdx.x; i < NNE/64; i += 256) {
        unsigned int k = ford(g_W[base + i]);
        if ((k >> 16) == hi) atomicAdd(&g_hist[2*BB*256 + b*256 + ((k >> 8) & 255u)], 1u);
    }
}

__global__ void collect_kernel() {
    __shared__ unsigned sh[258];
    int b = blockIdx.y;
    unsigned hi, need;
    compute_sel(b, 3, sh, hi, need);              // 24-bit prefix
    int base = blockIdx.x * (NNE/64);
    for (int i = threadIdx.x; i < NNE/64; i += 256) {
        int idx = base + i;
        unsigned int k = ford(g_W[b*NNE + idx]);
        if ((k >> 8) == hi) {
            unsigned int pos = atomicAdd(&g_cnt[b], 1u);
            if (pos < CAP)
                g_cand[b*CAP + pos] = ((unsigned long long)k << 32) | (unsigned int)idx;
        }
    }
}

__global__ void select_kernel() {
    __shared__ unsigned long long s[CAP];
    __shared__ unsigned sh[258];
    int b = blockIdx.x, t = threadIdx.x;
    unsigned hi, need;
    compute_sel(b, 3, sh, hi, need);
    unsigned int cnt = g_cnt[b]; if (cnt > CAP) cnt = CAP;
    for (unsigned int i = t; i < cnt; i += 256) s[i] = g_cand[b*CAP + i];
    __syncthreads();
    for (unsigned int i = t; i < cnt; i += 256) {
        unsigned long long k = s[i];
        unsigned int greater = 0;
        for (unsigned int j = 0; j < cnt; j++) greater += (s[j] > k);
        if (greater == need - 1) g_cut[b] = k;   // keys unique: exactly one hit
    }
}

__global__ void mask_kernel(float* __restrict__ out) {
    int i4 = (blockIdx.x * blockDim.x + threadIdx.x) * 4;
    if (i4 >= BB*NNE) return;
    int b = i4 >> 18;                          // NNE = 2^18
    unsigned long long cut = g_cut[b];
    float4 w = *(const float4*)&g_W[i4];
    unsigned base = (unsigned)(i4 & (NNE - 1));
    float4 o;
    o.x = ((((unsigned long long)ford(w.x) << 32) | (base + 0u)) >= cut) ? 1.0f : 0.0f;
    o.y = ((((unsigned long long)ford(w.y) << 32) | (base + 1u)) >= cut) ? 1.0f : 0.0f;
    o.z = ((((unsigned long long)ford(w.z) << 32) | (base + 2u)) >= cut) ? 1.0f : 0.0f;
    o.w = ((((unsigned long long)ford(w.w) << 32) | (base + 3u)) >= cut) ? 1.0f : 0.0f;
    *(float4*)&out[i4] = o;
}

// ---------------- launch ----------------------------------------------------
extern "C" void kernel_launch(void* const* d_in, const int* in_sizes, int n_in,
                              void* d_out, int out_size) {
    const float* x = (const float*)d_in[0];
    float* out = (float*)d_out;
    (void)in_sizes; (void)n_in; (void)out_size;

    stats_kernel<<<BB*NLEN/8, 256>>>(x);
    ecv_kernel<<<dim3(36, BB), 512>>>(x);
    gemm_nt_kernel<<<dim3(4, 8, BB), 256>>>();
    softmax_kernel<<<BB*NLEN, 128>>>();
    gemm_nn_kernel<<<dim3(4, 8, BB), 256>>>();
    hist2_kernel<<<dim3(64, BB), 256>>>();
    hist3_kernel<<<dim3(64, BB), 256>>>();
    collect_kernel<<<dim3(64, BB), 256>>>();
    select_kernel<<<BB, 256>>>();
    mask_kernel<<<(BB*NNE/4 + 255)/256, 256>>>(out);
}

// round 12
// speedup vs baseline: 1.3443x; 1.2108x over previous
#include <cuda_runtime.h>
#include <math.h>

#define BB 8
#define NLEN 512
#define CDIM 128
#define NNE (NLEN*NLEN)          // 262144 = 2^18
#define KSEL 43690               // NNE//6
#define FSCALE 0.08838834764831845f
#define CAP 4096

typedef unsigned long long u64;

#define FMA2(d, a, b, c) \
    asm("fma.rn.f32x2 %0, %1, %2, %3;" : "=l"(d) : "l"(a), "l"(b), "l"(c))
#define PACK2(d, x) \
    asm("mov.b64 %0, {%1, %1};" : "=l"(d) : "f"(x))
#define UNPACK2(lo, hi, v) \
    asm("mov.b64 {%0, %1}, %2;" : "=f"(lo), "=f"(hi) : "l"(v))

// ---------------- scratch (static device globals; no allocation) -------------
static __device__ float g_E [BB*NNE];
static __device__ float g_Ch[BB*NNE];
static __device__ float g_V [BB*NNE];
static __device__ float g_L [BB*NNE];   // logits, then attn after softmax
static __device__ float g_W [BB*NNE];
static __device__ float g_sq[BB*NLEN];
static __device__ float g_mu[BB*NLEN];
static __device__ float g_ds[BB*NLEN];
static __device__ unsigned int g_hist[3*BB*256];
static __device__ unsigned int g_cnt[BB];
static __device__ unsigned long long g_cand[BB*CAP];
static __device__ unsigned long long g_cut[BB];

__device__ __forceinline__ unsigned int ford(float f) {
    unsigned int u = __float_as_uint(f);
    return (u & 0x80000000u) ? ~u : (u | 0x80000000u);   // monotone float->uint
}

// ------- per-row stats (+ fused zeroing of hist/cnt state) ------------------
__global__ void stats_kernel(const float* __restrict__ x) {
    int z = blockIdx.x * 256 + threadIdx.x;
    if (z < 3*BB*256) g_hist[z] = 0u;
    if (z < BB)       g_cnt[z]  = 0u;

    int row  = blockIdx.x * 8 + (threadIdx.x >> 5);     // 4096 rows
    int lane = threadIdx.x & 31;
    const float* xr = x + (size_t)row * CDIM;
    float v[4]; float s = 0.f, ss = 0.f;
#pragma unroll
    for (int i = 0; i < 4; i++) {
        v[i] = xr[lane + 32*i];
        s  += v[i];
        ss += v[i]*v[i];
    }
#pragma unroll
    for (int o = 16; o; o >>= 1) {
        s  += __shfl_xor_sync(0xffffffffu, s,  o);
        ss += __shfl_xor_sync(0xffffffffu, ss, o);
    }
    float mu = s * (1.0f/CDIM);
    float cs = 0.f;
#pragma unroll
    for (int i = 0; i < 4; i++) { float d = v[i]-mu; cs += d*d; }
#pragma unroll
    for (int o = 16; o; o >>= 1) cs += __shfl_xor_sync(0xffffffffu, cs, o);
    if (lane == 0) { g_mu[row] = mu; g_sq[row] = ss; g_ds[row] = sqrtf(cs); }
}

// ---------------- E / Ch / V tiles: symmetric, upper-triangle blocks --------
// 512 threads, 2x4 micro-tile, FMA2 gram (bitwise == scalar fmaf chain).
__global__ void __launch_bounds__(512) ecv_kernel(const float* __restrict__ x) {
    __shared__ __align__(16) float Xn[64][68];
    __shared__ __align__(16) float Xm[64][68];
    int b  = blockIdx.y;
    int r = blockIdx.x, bi = 0;
    while (r >= 8 - bi) { r -= 8 - bi; bi++; }
    int bj = bi + r;
    int i0 = bi * 64, j0 = bj * 64;
    int t  = threadIdx.x;
    int tx = t & 15, ty = t >> 4;       // tx: col-quad 0..15, ty: row-pair 0..31
    const float* xb = x + (size_t)b * NLEN * CDIM;

    u64 g2[2][2];
    u64 zero2; { float z = 0.f; PACK2(zero2, z); }
    g2[0][0]=zero2; g2[0][1]=zero2; g2[1][0]=zero2; g2[1][1]=zero2;
    float ch[2][4];
#pragma unroll
    for (int i = 0; i < 2; i++)
#pragma unroll
        for (int j = 0; j < 4; j++) ch[i][j] = 0.f;

    for (int ph = 0; ph < 2; ph++) {
        int cbase = ph * 64;
#pragma unroll
        for (int it = 0; it < 2; it++) {
            int idx = t + 512*it;            // 0..1023 float4 slots
            int rr  = idx >> 4;              // 0..63
            int c4  = (idx & 15) * 4;        // 0..60
            float4 a = *(const float4*)&xb[(size_t)(i0+rr)*CDIM + cbase + c4];
            Xn[c4+0][rr] = a.x; Xn[c4+1][rr] = a.y; Xn[c4+2][rr] = a.z; Xn[c4+3][rr] = a.w;
            float4 m = *(const float4*)&xb[(size_t)(j0+rr)*CDIM + cbase + c4];
            Xm[c4+0][rr] = m.x; Xm[c4+1][rr] = m.y; Xm[c4+2][rr] = m.z; Xm[c4+3][rr] = m.w;
        }
        __syncthreads();
#pragma unroll 4
        for (int c = 0; c < 64; c++) {
            float2 a2 = *(const float2*)&Xn[c][ty*2];
            ulonglong2 bp = *(const ulonglong2*)&Xm[c][tx*4];
            float b0, b1, b2, b3;
            UNPACK2(b0, b1, bp.x);
            UNPACK2(b2, b3, bp.y);
            u64 ax, ay;
            PACK2(ax, a2.x); PACK2(ay, a2.y);
            FMA2(g2[0][0], ax, bp.x, g2[0][0]);
            FMA2(g2[0][1], ax, bp.y, g2[0][1]);
            FMA2(g2[1][0], ay, bp.x, g2[1][0]);
            FMA2(g2[1][1], ay, bp.y, g2[1][1]);
            ch[0][0] = fmaxf(ch[0][0], fabsf(a2.x - b0));
            ch[0][1] = fmaxf(ch[0][1], fabsf(a2.x - b1));
            ch[0][2] = fmaxf(ch[0][2], fabsf(a2.x - b2));
            ch[0][3] = fmaxf(ch[0][3], fabsf(a2.x - b3));
            ch[1][0] = fmaxf(ch[1][0], fabsf(a2.y - b0));
            ch[1][1] = fmaxf(ch[1][1], fabsf(a2.y - b1));
            ch[1][2] = fmaxf(ch[1][2], fabsf(a2.y - b2));
            ch[1][3] = fmaxf(ch[1][3], fabsf(a2.y - b3));
        }
        __syncthreads();
    }

    float g[2][4];
    UNPACK2(g[0][0], g[0][1], g2[0][0]);
    UNPACK2(g[0][2], g[0][3], g2[0][1]);
    UNPACK2(g[1][0], g[1][1], g2[1][0]);
    UNPACK2(g[1][2], g[1][3], g2[1][1]);

    int ib = b*NLEN + i0 + ty*2;
    int jb = b*NLEN + j0 + tx*4;
    float sqi[2], mui[2], dsi[2], sqj[4], muj[4], dsj[4];
#pragma unroll
    for (int q = 0; q < 2; q++) {
        sqi[q] = g_sq[ib+q]; mui[q] = g_mu[ib+q]; dsi[q] = g_ds[ib+q];
    }
#pragma unroll
    for (int q = 0; q < 4; q++) {
        sqj[q] = g_sq[jb+q]; muj[q] = g_mu[jb+q]; dsj[q] = g_ds[jb+q];
    }
    float e[2][4], v[2][4];
#pragma unroll
    for (int i = 0; i < 2; i++)
#pragma unroll
        for (int j = 0; j < 4; j++) {
            float d2 = sqi[i] + sqj[j] - 2.0f * g[i][j];
            e[i][j] = sqrtf(fmaxf(d2, 0.0f));
            float cov = g[i][j] - (float)CDIM * mui[i] * muj[j];
            float vv  = cov / (dsi[i] * dsj[j]);
            v[i][j] = fminf(fmaxf(vv, -1.0f), 1.0f);
        }
#pragma unroll
    for (int i = 0; i < 2; i++) {
        size_t off = (size_t)b*NNE + (size_t)(i0 + ty*2 + i)*NLEN + j0 + tx*4;
        *(float4*)&g_E [off] = make_float4(e[i][0], e[i][1], e[i][2], e[i][3]);
        *(float4*)&g_Ch[off] = make_float4(ch[i][0], ch[i][1], ch[i][2], ch[i][3]);
        *(float4*)&g_V [off] = make_float4(v[i][0], v[i][1], v[i][2], v[i][3]);
    }
    if (bi != bj) {
        size_t mbase = (size_t)b*NNE;
#pragma unroll
        for (int j = 0; j < 4; j++) {
            size_t rowoff = mbase + (size_t)(j0 + tx*4 + j)*NLEN + i0 + ty*2;
            float2 me = make_float2(e[0][j], e[1][j]);
            float2 mc = make_float2(ch[0][j], ch[1][j]);
            float2 mv = make_float2(v[0][j], v[1][j]);
            *(float2*)&g_E [rowoff] = me;
            *(float2*)&g_Ch[rowoff] = mc;
            *(float2*)&g_V [rowoff] = mv;
        }
    }
}

// ------------- 128x128x8 double-buffered fp32 GEMM (FFMA2 packed) -----------
// FROZEN: the proven R4 body. Full K=512, sequential per-output accumulation.
// TRANSB=true : C[n,m] = sum_k A[n,k] * B[m,k]  (NT)
// TRANSB=false: C[n,k] = sum_m A[n,m] * B[m,k]  (NN)
// HIST: fuse radix pass-0 histogram of ford(C)>>24 into the epilogue.
template<bool TRANSB, bool HIST>
__device__ __forceinline__ void gemm128_body(const float* __restrict__ A,
                                             const float* __restrict__ B,
                                             float* __restrict__ C, int batch) {
    __shared__ __align__(16) float As[2][8][132];
    __shared__ __align__(16) float Bs[2][8][132];
    __shared__ unsigned hist[HIST ? 256 : 1];
    int i0 = blockIdx.y * 128, j0 = blockIdx.x * 128;
    int t  = threadIdx.x;
    int tx = t & 15, ty = t >> 4;
    int ar = t >> 1, ac = (t & 1) * 4;      // A (and NT-B) loader: row, k-offset
    int bk = t >> 5, bc = (t & 31) * 4;     // NN-B loader: k-row, col-offset

    if (HIST) hist[t] = 0u;

    // packed accumulators: acc2[i][jp] holds columns (2*jp, 2*jp+1) of row i
    u64 acc2[8][4];
    u64 zero2; { float z = 0.f; PACK2(zero2, z); }
#pragma unroll
    for (int i = 0; i < 8; i++)
#pragma unroll
        for (int j = 0; j < 4; j++) acc2[i][j] = zero2;

    float4 pa, pb;
    pa = *(const float4*)&A[(size_t)(i0+ar)*NLEN + ac];
    if (TRANSB) pb = *(const float4*)&B[(size_t)(j0+ar)*NLEN + ac];
    else        pb = *(const float4*)&B[(size_t)bk*NLEN + j0 + bc];
    As[0][ac+0][ar]=pa.x; As[0][ac+1][ar]=pa.y; As[0][ac+2][ar]=pa.z; As[0][ac+3][ar]=pa.w;
    if (TRANSB) { Bs[0][ac+0][ar]=pb.x; Bs[0][ac+1][ar]=pb.y; Bs[0][ac+2][ar]=pb.z; Bs[0][ac+3][ar]=pb.w; }
    else        { *(float4*)&Bs[0][bk][bc] = pb; }
    __syncthreads();

    int cur = 0;
    for (int kb = 0; kb < NLEN; kb += 8) {
        bool notlast = (kb + 8 < NLEN);
        if (notlast) {
            pa = *(const float4*)&A[(size_t)(i0+ar)*NLEN + kb + 8 + ac];
            if (TRANSB) pb = *(const float4*)&B[(size_t)(j0+ar)*NLEN + kb + 8 + ac];
            else        pb = *(const float4*)&B[(size_t)(kb+8+bk)*NLEN + j0 + bc];
        }
#pragma unroll
        for (int kk = 0; kk < 8; kk++) {
            float a[8];
            *(float4*)&a[0] = *(const float4*)&As[cur][kk][ty*4];
            *(float4*)&a[4] = *(const float4*)&As[cur][kk][ty*4 + 64];
            ulonglong2 blo = *(const ulonglong2*)&Bs[cur][kk][tx*4];
            ulonglong2 bhi = *(const ulonglong2*)&Bs[cur][kk][tx*4 + 64];
#pragma unroll
            for (int i = 0; i < 8; i++) {
                u64 aa; PACK2(aa, a[i]);
                FMA2(acc2[i][0], aa, blo.x, acc2[i][0]);
                FMA2(acc2[i][1], aa, blo.y, acc2[i][1]);
                FMA2(acc2[i][2], aa, bhi.x, acc2[i][2]);
                FMA2(acc2[i][3], aa, bhi.y, acc2[i][3]);
            }
        }
        if (notlast) {
            int nb = cur ^ 1;
            As[nb][ac+0][ar]=pa.x; As[nb][ac+1][ar]=pa.y; As[nb][ac+2][ar]=pa.z; As[nb][ac+3][ar]=pa.w;
            if (TRANSB) { Bs[nb][ac+0][ar]=pb.x; Bs[nb][ac+1][ar]=pb.y; Bs[nb][ac+2][ar]=pb.z; Bs[nb][ac+3][ar]=pb.w; }
            else        { *(float4*)&Bs[nb][bk][bc] = pb; }
            __syncthreads();
            cur = nb;
        }
    }
#pragma unroll
    for (int gi = 0; gi < 2; gi++)
#pragma unroll
    for (int i = 0; i < 4; i++) {
        int row = i0 + gi*64 + ty*4 + i;
#pragma unroll
        for (int gj = 0; gj < 2; gj++) {
            float4 rv;
            UNPACK2(rv.x, rv.y, acc2[gi*4+i][gj*2+0]);
            UNPACK2(rv.z, rv.w, acc2[gi*4+i][gj*2+1]);
            *(float4*)&C[(size_t)row*NLEN + j0 + gj*64 + tx*4] = rv;
            if (HIST) {
                atomicAdd(&hist[ford(rv.x) >> 24], 1u);
                atomicAdd(&hist[ford(rv.y) >> 24], 1u);
                atomicAdd(&hist[ford(rv.z) >> 24], 1u);
                atomicAdd(&hist[ford(rv.w) >> 24], 1u);
            }
        }
    }
    if (HIST) {
        __syncthreads();
        if (hist[t]) atomicAdd(&g_hist[0*BB*256 + batch*256 + t], hist[t]);
    }
}

__global__ void __launch_bounds__(256) gemm_nt_kernel() {
    size_t o = (size_t)blockIdx.z * NNE;
    gemm128_body<true, false>(g_E + o, g_Ch + o, g_L + o, blockIdx.z);
}

__global__ void __launch_bounds__(256) gemm_nn_kernel() {
    size_t o = (size_t)blockIdx.z * NNE;
    gemm128_body<false, true>(g_L + o, g_V + o, g_W + o, blockIdx.z);
}

// ---------------- row softmax of L*SCALE (in place) -------------------------
__global__ void softmax_kernel() {
    __shared__ float red[128];
    int row = blockIdx.x;                          // 0..4095
    float* p = g_L + (size_t)row * NLEN;
    int t = threadIdx.x;
    float v[4]; float mx = -3.4e38f;
#pragma unroll
    for (int q = 0; q < 4; q++) { v[q] = p[t + 128*q] * FSCALE; mx = fmaxf(mx, v[q]); }
    red[t] = mx; __syncthreads();
    for (int o = 64; o; o >>= 1) { if (t < o) red[t] = fmaxf(red[t], red[t+o]); __syncthreads(); }
    mx = red[0]; __syncthreads();
    float e[4]; float s = 0.f;
#pragma unroll
    for (int q = 0; q < 4; q++) { e[q] = expf(v[q] - mx); s += e[q]; }
    red[t] = s; __syncthreads();
    for (int o = 64; o; o >>= 1) { if (t < o) red[t] += red[t+o]; __syncthreads(); }
    s = red[0];
#pragma unroll
    for (int q = 0; q < 4; q++) p[t + 128*q] = e[q] / s;
}

// ---------------- selection: radix passes; prefix recomputed in-block -------
__device__ void compute_sel(int b, int npass, unsigned* sh,
                            unsigned& hi_out, unsigned& need_out) {
    int t = threadIdx.x;
    unsigned hi = 0u, need = (unsigned)KSEL;
    for (int p = 0; p < npass; p++) {
        sh[t] = g_hist[p*BB*256 + b*256 + t];
        __syncthreads();
        for (int off = 1; off < 256; off <<= 1) {
            unsigned add = (t + off < 256) ? sh[t + off] : 0u;
            __syncthreads();
            sh[t] += add;
            __syncthreads();
        }
        unsigned S     = sh[t];
        unsigned Snext = (t < 255) ? sh[t + 1] : 0u;
        __syncthreads();
        if (S >= need && Snext < need) { sh[256] = (unsigned)t; sh[257] = need - Snext; }
        __syncthreads();
        hi   = (hi << 8) | sh[256];
        need = sh[257];
        __syncthreads();
    }
    hi_out = hi; need_out = need;
}

__global__ void hist2_kernel() {
    __shared__ unsigned sh[258];
    int b = blockIdx.y;
    unsigned hi, need;
    compute_sel(b, 1, sh, hi, need);              // 8-bit prefix
    int base = b*NNE + blockIdx.x * (NNE/64);
    for (int it = 0; it < 4; it++) {
        int i4 = (threadIdx.x + 256*it) * 4;      // 0..16380
        float4 w = *(const float4*)&g_W[base + i4];
        unsigned k0 = ford(w.x), k1 = ford(w.y), k2 = ford(w.z), k3 = ford(w.w);
        if ((k0 >> 24) == hi) atomicAdd(&g_hist[1*BB*256 + b*256 + ((k0 >> 16) & 255u)], 1u);
        if ((k1 >> 24) == hi) atomicAdd(&g_hist[1*BB*256 + b*256 + ((k1 >> 16) & 255u)], 1u);
        if ((k2 >> 24) == hi) atomicAdd(&g_hist[1*BB*256 + b*256 + ((k2 >> 16) & 255u)], 1u);
        if ((k3 >> 24) == hi) atomicAdd(&g_hist[1*BB*256 + b*256 + ((k3 >> 16) & 255u)], 1u);
    }
}

__global__ void hist3_kernel() {
    __shared__ unsigned sh[258];
    int b = blockIdx.y;
    unsigned hi, need;
    compute_sel(b, 2, sh, hi, need);              // 16-bit prefix
    int base = b*NNE + blockIdx.x * (NNE/64);
    for (int it = 0; it < 4; it++) {
        int i4 = (threadIdx.x + 256*it) * 4;
        float4 w = *(const float4*)&g_W[base + i4];
        unsigned k0 = ford(w.x), k1 = ford(w.y), k2 = ford(w.z), k3 = ford(w.w);
        if ((k0 >> 16) == hi) atomicAdd(&g_hist[2*BB*256 + b*256 + ((k0 >> 8) & 255u)], 1u);
        if ((k1 >> 16) == hi) atomicAdd(&g_hist[2*BB*256 + b*256 + ((k1 >> 8) & 255u)], 1u);
        if ((k2 >> 16) == hi) atomicAdd(&g_hist[2*BB*256 + b*256 + ((k2 >> 8) & 255u)], 1u);
        if ((k3 >> 16) == hi) atomicAdd(&g_hist[2*BB*256 + b*256 + ((k3 >> 8) & 255u)], 1u);
    }
}

__global__ void collect_kernel() {
    __shared__ unsigned sh[258];
    int b = blockIdx.y;
    unsigned hi, need;
    compute_sel(b, 3, sh, hi, need);              // 24-bit prefix
    int base = blockIdx.x * (NNE/64);
    for (int it = 0; it < 4; it++) {
        int i4 = base + (threadIdx.x + 256*it) * 4;   // flat idx within batch
        float4 w = *(const float4*)&g_W[b*NNE + i4];
        unsigned k[4] = { ford(w.x), ford(w.y), ford(w.z), ford(w.w) };
#pragma unroll
        for (int j = 0; j < 4; j++) {
            if ((k[j] >> 8) == hi) {
                unsigned int pos = atomicAdd(&g_cnt[b], 1u);
                if (pos < CAP)
                    g_cand[b*CAP + pos] =
                        ((unsigned long long)k[j] << 32) | (unsigned int)(i4 + j);
            }
        }
    }
}

__global__ void select_kernel() {
    __shared__ unsigned long long s[CAP];
    __shared__ unsigned sh[258];
    int b = blockIdx.x, t = threadIdx.x;
    unsigned hi, need;
    compute_sel(b, 3, sh, hi, need);
    unsigned int cnt = g_cnt[b]; if (cnt > CAP) cnt = CAP;
    for (unsigned int i = t; i < cnt; i += 256) s[i] = g_cand[b*CAP + i];
    __syncthreads();
    for (unsigned int i = t; i < cnt; i += 256) {
        unsigned long long k = s[i];
        unsigned int greater = 0;
        for (unsigned int j = 0; j < cnt; j++) greater += (s[j] > k);
        if (greater == need - 1) g_cut[b] = k;   // keys unique: exactly one hit
    }
}

__global__ void mask_kernel(float* __restrict__ out) {
    int i4 = (blockIdx.x * blockDim.x + threadIdx.x) * 4;
    if (i4 >= BB*NNE) return;
    int b = i4 >> 18;                          // NNE = 2^18
    unsigned long long cut = g_cut[b];
    float4 w = *(const float4*)&g_W[i4];
    unsigned base = (unsigned)(i4 & (NNE - 1));
    float4 o;
    o.x = ((((unsigned long long)ford(w.x) << 32) | (base + 0u)) >= cut) ? 1.0f : 0.0f;
    o.y = ((((unsigned long long)ford(w.y) << 32) | (base + 1u)) >= cut) ? 1.0f : 0.0f;
    o.z = ((((unsigned long long)ford(w.z) << 32) | (base + 2u)) >= cut) ? 1.0f : 0.0f;
    o.w = ((((unsigned long long)ford(w.w) << 32) | (base + 3u)) >= cut) ? 1.0f : 0.0f;
    *(float4*)&out[i4] = o;
}

// ---------------- launch ----------------------------------------------------
extern "C" void kernel_launch(void* const* d_in, const int* in_sizes, int n_in,
                              void* d_out, int out_size) {
    const float* x = (const float*)d_in[0];
    float* out = (float*)d_out;
    (void)in_sizes; (void)n_in; (void)out_size;

    stats_kernel<<<BB*NLEN/8, 256>>>(x);
    ecv_kernel<<<dim3(36, BB), 512>>>(x);
    gemm_nt_kernel<<<dim3(4, 4, BB), 256>>>();
    softmax_kernel<<<BB*NLEN, 128>>>();
    gemm_nn_kernel<<<dim3(4, 4, BB), 256>>>();
    hist2_kernel<<<dim3(64, BB), 256>>>();
    hist3_kernel<<<dim3(64, BB), 256>>>();
    collect_kernel<<<dim3(64, BB), 256>>>();
    select_kernel<<<BB, 256>>>();
    mask_kernel<<<(BB*NNE/4 + 255)/256, 256>>>(out);
}

// round 13
// speedup vs baseline: 1.3690x; 1.0184x over previous
#include <cuda_runtime.h>
#include <math.h>

#define BB 8
#define NLEN 512
#define CDIM 128
#define NNE (NLEN*NLEN)          // 262144 = 2^18
#define KSEL 43690               // NNE//6
#define FSCALE 0.08838834764831845f
#define CAP 4096
#define CAP2 32768

typedef unsigned long long u64;

#define FMA2(d, a, b, c) \
    asm("fma.rn.f32x2 %0, %1, %2, %3;" : "=l"(d) : "l"(a), "l"(b), "l"(c))
#define PACK2(d, x) \
    asm("mov.b64 %0, {%1, %1};" : "=l"(d) : "f"(x))
#define UNPACK2(lo, hi, v) \
    asm("mov.b64 {%0, %1}, %2;" : "=f"(lo), "=f"(hi) : "l"(v))

// ---------------- scratch (static device globals; no allocation) -------------
static __device__ float g_E [BB*NNE];
static __device__ float g_Ch[BB*NNE];
static __device__ float g_V [BB*NNE];
static __device__ float g_L [BB*NNE];   // logits, then attn after softmax
static __device__ float g_W [BB*NNE];
static __device__ float g_sq[BB*NLEN];
static __device__ float g_mu[BB*NLEN];
static __device__ float g_ds[BB*NLEN];
static __device__ unsigned int g_hist[3*BB*256];
static __device__ unsigned int g_cnt[BB];
static __device__ unsigned long long g_cand[BB*CAP2];
static __device__ unsigned long long g_cut[BB];

__device__ __forceinline__ unsigned int ford(float f) {
    unsigned int u = __float_as_uint(f);
    return (u & 0x80000000u) ? ~u : (u | 0x80000000u);   // monotone float->uint
}

// ------- per-row stats (+ fused zeroing of hist/cnt state) ------------------
__global__ void stats_kernel(const float* __restrict__ x) {
    int z = blockIdx.x * 256 + threadIdx.x;
    if (z < 3*BB*256) g_hist[z] = 0u;
    if (z < BB)       g_cnt[z]  = 0u;

    int row  = blockIdx.x * 8 + (threadIdx.x >> 5);     // 4096 rows
    int lane = threadIdx.x & 31;
    const float* xr = x + (size_t)row * CDIM;
    float v[4]; float s = 0.f, ss = 0.f;
#pragma unroll
    for (int i = 0; i < 4; i++) {
        v[i] = xr[lane + 32*i];
        s  += v[i];
        ss += v[i]*v[i];
    }
#pragma unroll
    for (int o = 16; o; o >>= 1) {
        s  += __shfl_xor_sync(0xffffffffu, s,  o);
        ss += __shfl_xor_sync(0xffffffffu, ss, o);
    }
    float mu = s * (1.0f/CDIM);
    float cs = 0.f;
#pragma unroll
    for (int i = 0; i < 4; i++) { float d = v[i]-mu; cs += d*d; }
#pragma unroll
    for (int o = 16; o; o >>= 1) cs += __shfl_xor_sync(0xffffffffu, cs, o);
    if (lane == 0) { g_mu[row] = mu; g_sq[row] = ss; g_ds[row] = sqrtf(cs); }
}

// ---------------- E / Ch / V tiles: symmetric, upper-triangle blocks --------
// 512 threads, 2x4 micro-tile, FMA2 gram (bitwise == scalar fmaf chain).
__global__ void __launch_bounds__(512) ecv_kernel(const float* __restrict__ x) {
    __shared__ __align__(16) float Xn[64][68];
    __shared__ __align__(16) float Xm[64][68];
    int b  = blockIdx.y;
    int r = blockIdx.x, bi = 0;
    while (r >= 8 - bi) { r -= 8 - bi; bi++; }
    int bj = bi + r;
    int i0 = bi * 64, j0 = bj * 64;
    int t  = threadIdx.x;
    int tx = t & 15, ty = t >> 4;       // tx: col-quad 0..15, ty: row-pair 0..31
    const float* xb = x + (size_t)b * NLEN * CDIM;

    u64 g2[2][2];
    u64 zero2; { float z = 0.f; PACK2(zero2, z); }
    g2[0][0]=zero2; g2[0][1]=zero2; g2[1][0]=zero2; g2[1][1]=zero2;
    float ch[2][4];
#pragma unroll
    for (int i = 0; i < 2; i++)
#pragma unroll
        for (int j = 0; j < 4; j++) ch[i][j] = 0.f;

    for (int ph = 0; ph < 2; ph++) {
        int cbase = ph * 64;
#pragma unroll
        for (int it = 0; it < 2; it++) {
            int idx = t + 512*it;            // 0..1023 float4 slots
            int rr  = idx >> 4;              // 0..63
            int c4  = (idx & 15) * 4;        // 0..60
            float4 a = *(const float4*)&xb[(size_t)(i0+rr)*CDIM + cbase + c4];
            Xn[c4+0][rr] = a.x; Xn[c4+1][rr] = a.y; Xn[c4+2][rr] = a.z; Xn[c4+3][rr] = a.w;
            float4 m = *(const float4*)&xb[(size_t)(j0+rr)*CDIM + cbase + c4];
            Xm[c4+0][rr] = m.x; Xm[c4+1][rr] = m.y; Xm[c4+2][rr] = m.z; Xm[c4+3][rr] = m.w;
        }
        __syncthreads();
#pragma unroll 4
        for (int c = 0; c < 64; c++) {
            float2 a2 = *(const float2*)&Xn[c][ty*2];
            ulonglong2 bp = *(const ulonglong2*)&Xm[c][tx*4];
            float b0, b1, b2, b3;
            UNPACK2(b0, b1, bp.x);
            UNPACK2(b2, b3, bp.y);
            u64 ax, ay;
            PACK2(ax, a2.x); PACK2(ay, a2.y);
            FMA2(g2[0][0], ax, bp.x, g2[0][0]);
            FMA2(g2[0][1], ax, bp.y, g2[0][1]);
            FMA2(g2[1][0], ay, bp.x, g2[1][0]);
            FMA2(g2[1][1], ay, bp.y, g2[1][1]);
            ch[0][0] = fmaxf(ch[0][0], fabsf(a2.x - b0));
            ch[0][1] = fmaxf(ch[0][1], fabsf(a2.x - b1));
            ch[0][2] = fmaxf(ch[0][2], fabsf(a2.x - b2));
            ch[0][3] = fmaxf(ch[0][3], fabsf(a2.x - b3));
            ch[1][0] = fmaxf(ch[1][0], fabsf(a2.y - b0));
            ch[1][1] = fmaxf(ch[1][1], fabsf(a2.y - b1));
            ch[1][2] = fmaxf(ch[1][2], fabsf(a2.y - b2));
            ch[1][3] = fmaxf(ch[1][3], fabsf(a2.y - b3));
        }
        __syncthreads();
    }

    float g[2][4];
    UNPACK2(g[0][0], g[0][1], g2[0][0]);
    UNPACK2(g[0][2], g[0][3], g2[0][1]);
    UNPACK2(g[1][0], g[1][1], g2[1][0]);
    UNPACK2(g[1][2], g[1][3], g2[1][1]);

    int ib = b*NLEN + i0 + ty*2;
    int jb = b*NLEN + j0 + tx*4;
    float sqi[2], mui[2], dsi[2], sqj[4], muj[4], dsj[4];
#pragma unroll
    for (int q = 0; q < 2; q++) {
        sqi[q] = g_sq[ib+q]; mui[q] = g_mu[ib+q]; dsi[q] = g_ds[ib+q];
    }
#pragma unroll
    for (int q = 0; q < 4; q++) {
        sqj[q] = g_sq[jb+q]; muj[q] = g_mu[jb+q]; dsj[q] = g_ds[jb+q];
    }
    float e[2][4], v[2][4];
#pragma unroll
    for (int i = 0; i < 2; i++)
#pragma unroll
        for (int j = 0; j < 4; j++) {
            float d2 = sqi[i] + sqj[j] - 2.0f * g[i][j];
            e[i][j] = sqrtf(fmaxf(d2, 0.0f));
            float cov = g[i][j] - (float)CDIM * mui[i] * muj[j];
            float vv  = cov / (dsi[i] * dsj[j]);
            v[i][j] = fminf(fmaxf(vv, -1.0f), 1.0f);
        }
#pragma unroll
    for (int i = 0; i < 2; i++) {
        size_t off = (size_t)b*NNE + (size_t)(i0 + ty*2 + i)*NLEN + j0 + tx*4;
        *(float4*)&g_E [off] = make_float4(e[i][0], e[i][1], e[i][2], e[i][3]);
        *(float4*)&g_Ch[off] = make_float4(ch[i][0], ch[i][1], ch[i][2], ch[i][3]);
        *(float4*)&g_V [off] = make_float4(v[i][0], v[i][1], v[i][2], v[i][3]);
    }
    if (bi != bj) {
        size_t mbase = (size_t)b*NNE;
#pragma unroll
        for (int j = 0; j < 4; j++) {
            size_t rowoff = mbase + (size_t)(j0 + tx*4 + j)*NLEN + i0 + ty*2;
            float2 me = make_float2(e[0][j], e[1][j]);
            float2 mc = make_float2(ch[0][j], ch[1][j]);
            float2 mv = make_float2(v[0][j], v[1][j]);
            *(float2*)&g_E [rowoff] = me;
            *(float2*)&g_Ch[rowoff] = mc;
            *(float2*)&g_V [rowoff] = mv;
        }
    }
}

// ------------- 128x128x8 double-buffered fp32 GEMM (FFMA2 packed) -----------
// FROZEN: the proven R4 body. Full K=512, sequential per-output accumulation.
// TRANSB=true : C[n,m] = sum_k A[n,k] * B[m,k]  (NT)
// TRANSB=false: C[n,k] = sum_m A[n,m] * B[m,k]  (NN)
// HIST: fuse radix pass-0 histogram of ford(C)>>24 into the epilogue.
template<bool TRANSB, bool HIST>
__device__ __forceinline__ void gemm128_body(const float* __restrict__ A,
                                             const float* __restrict__ B,
                                             float* __restrict__ C, int batch) {
    __shared__ __align__(16) float As[2][8][132];
    __shared__ __align__(16) float Bs[2][8][132];
    __shared__ unsigned hist[HIST ? 256 : 1];
    int i0 = blockIdx.y * 128, j0 = blockIdx.x * 128;
    int t  = threadIdx.x;
    int tx = t & 15, ty = t >> 4;
    int ar = t >> 1, ac = (t & 1) * 4;      // A (and NT-B) loader: row, k-offset
    int bk = t >> 5, bc = (t & 31) * 4;     // NN-B loader: k-row, col-offset

    if (HIST) hist[t] = 0u;

    // packed accumulators: acc2[i][jp] holds columns (2*jp, 2*jp+1) of row i
    u64 acc2[8][4];
    u64 zero2; { float z = 0.f; PACK2(zero2, z); }
#pragma unroll
    for (int i = 0; i < 8; i++)
#pragma unroll
        for (int j = 0; j < 4; j++) acc2[i][j] = zero2;

    float4 pa, pb;
    pa = *(const float4*)&A[(size_t)(i0+ar)*NLEN + ac];
    if (TRANSB) pb = *(const float4*)&B[(size_t)(j0+ar)*NLEN + ac];
    else        pb = *(const float4*)&B[(size_t)bk*NLEN + j0 + bc];
    As[0][ac+0][ar]=pa.x; As[0][ac+1][ar]=pa.y; As[0][ac+2][ar]=pa.z; As[0][ac+3][ar]=pa.w;
    if (TRANSB) { Bs[0][ac+0][ar]=pb.x; Bs[0][ac+1][ar]=pb.y; Bs[0][ac+2][ar]=pb.z; Bs[0][ac+3][ar]=pb.w; }
    else        { *(float4*)&Bs[0][bk][bc] = pb; }
    __syncthreads();

    int cur = 0;
    for (int kb = 0; kb < NLEN; kb += 8) {
        bool notlast = (kb + 8 < NLEN);
        if (notlast) {
            pa = *(const float4*)&A[(size_t)(i0+ar)*NLEN + kb + 8 + ac];
            if (TRANSB) pb = *(const float4*)&B[(size_t)(j0+ar)*NLEN + kb + 8 + ac];
            else        pb = *(const float4*)&B[(size_t)(kb+8+bk)*NLEN + j0 + bc];
        }
#pragma unroll
        for (int kk = 0; kk < 8; kk++) {
            float a[8];
            *(float4*)&a[0] = *(const float4*)&As[cur][kk][ty*4];
            *(float4*)&a[4] = *(const float4*)&As[cur][kk][ty*4 + 64];
            ulonglong2 blo = *(const ulonglong2*)&Bs[cur][kk][tx*4];
            ulonglong2 bhi = *(const ulonglong2*)&Bs[cur][kk][tx*4 + 64];
#pragma unroll
            for (int i = 0; i < 8; i++) {
                u64 aa; PACK2(aa, a[i]);
                FMA2(acc2[i][0], aa, blo.x, acc2[i][0]);
                FMA2(acc2[i][1], aa, blo.y, acc2[i][1]);
                FMA2(acc2[i][2], aa, bhi.x, acc2[i][2]);
                FMA2(acc2[i][3], aa, bhi.y, acc2[i][3]);
            }
        }
        if (notlast) {
            int nb = cur ^ 1;
            As[nb][ac+0][ar]=pa.x; As[nb][ac+1][ar]=pa.y; As[nb][ac+2][ar]=pa.z; As[nb][ac+3][ar]=pa.w;
            if (TRANSB) { Bs[nb][ac+0][ar]=pb.x; Bs[nb][ac+1][ar]=pb.y; Bs[nb][ac+2][ar]=pb.z; Bs[nb][ac+3][ar]=pb.w; }
            else        { *(float4*)&Bs[nb][bk][bc] = pb; }
            __syncthreads();
            cur = nb;
        }
    }
#pragma unroll
    for (int gi = 0; gi < 2; gi++)
#pragma unroll
    for (int i = 0; i < 4; i++) {
        int row = i0 + gi*64 + ty*4 + i;
#pragma unroll
        for (int gj = 0; gj < 2; gj++) {
            float4 rv;
            UNPACK2(rv.x, rv.y, acc2[gi*4+i][gj*2+0]);
            UNPACK2(rv.z, rv.w, acc2[gi*4+i][gj*2+1]);
            *(float4*)&C[(size_t)row*NLEN + j0 + gj*64 + tx*4] = rv;
            if (HIST) {
                atomicAdd(&hist[ford(rv.x) >> 24], 1u);
                atomicAdd(&hist[ford(rv.y) >> 24], 1u);
                atomicAdd(&hist[ford(rv.z) >> 24], 1u);
                atomicAdd(&hist[ford(rv.w) >> 24], 1u);
            }
        }
    }
    if (HIST) {
        __syncthreads();
        if (hist[t]) atomicAdd(&g_hist[0*BB*256 + batch*256 + t], hist[t]);
    }
}

__global__ void __launch_bounds__(256) gemm_nt_kernel() {
    size_t o = (size_t)blockIdx.z * NNE;
    gemm128_body<true, false>(g_E + o, g_Ch + o, g_L + o, blockIdx.z);
}

__global__ void __launch_bounds__(256) gemm_nn_kernel() {
    size_t o = (size_t)blockIdx.z * NNE;
    gemm128_body<false, true>(g_L + o, g_V + o, g_W + o, blockIdx.z);
}

// ---------------- row softmax of L*SCALE (in place) -------------------------
__global__ void softmax_kernel() {
    __shared__ float red[128];
    int row = blockIdx.x;                          // 0..4095
    float* p = g_L + (size_t)row * NLEN;
    int t = threadIdx.x;
    float v[4]; float mx = -3.4e38f;
#pragma unroll
    for (int q = 0; q < 4; q++) { v[q] = p[t + 128*q] * FSCALE; mx = fmaxf(mx, v[q]); }
    red[t] = mx; __syncthreads();
    for (int o = 64; o; o >>= 1) { if (t < o) red[t] = fmaxf(red[t], red[t+o]); __syncthreads(); }
    mx = red[0]; __syncthreads();
    float e[4]; float s = 0.f;
#pragma unroll
    for (int q = 0; q < 4; q++) { e[q] = expf(v[q] - mx); s += e[q]; }
    red[t] = s; __syncthreads();
    for (int o = 64; o; o >>= 1) { if (t < o) red[t] += red[t+o]; __syncthreads(); }
    s = red[0];
#pragma unroll
    for (int q = 0; q < 4; q++) p[t + 128*q] = e[q] / s;
}

// ---------------- selection: radix passes; prefix recomputed in-block -------
__device__ void compute_sel(int b, int npass, unsigned* sh,
                            unsigned& hi_out, unsigned& need_out) {
    int t = threadIdx.x;
    unsigned hi = 0u, need = (unsigned)KSEL;
    for (int p = 0; p < npass; p++) {
        sh[t] = g_hist[p*BB*256 + b*256 + t];
        __syncthreads();
        for (int off = 1; off < 256; off <<= 1) {
            unsigned add = (t + off < 256) ? sh[t + off] : 0u;
            __syncthreads();
            sh[t] += add;
            __syncthreads();
        }
        unsigned S     = sh[t];
        unsigned Snext = (t < 255) ? sh[t + 1] : 0u;
        __syncthreads();
        if (S >= need && Snext < need) { sh[256] = (unsigned)t; sh[257] = need - Snext; }
        __syncthreads();
        hi   = (hi << 8) | sh[256];
        need = sh[257];
        __syncthreads();
    }
    hi_out = hi; need_out = need;
}

__global__ void hist2_kernel() {
    __shared__ unsigned sh[258];
    int b = blockIdx.y;
    unsigned hi, need;
    compute_sel(b, 1, sh, hi, need);              // 8-bit prefix
    int base = b*NNE + blockIdx.x * (NNE/64);
    for (int it = 0; it < 4; it++) {
        int i4 = (threadIdx.x + 256*it) * 4;      // 0..16380
        float4 w = *(const float4*)&g_W[base + i4];
        unsigned k0 = ford(w.x), k1 = ford(w.y), k2 = ford(w.z), k3 = ford(w.w);
        if ((k0 >> 24) == hi) atomicAdd(&g_hist[1*BB*256 + b*256 + ((k0 >> 16) & 255u)], 1u);
        if ((k1 >> 24) == hi) atomicAdd(&g_hist[1*BB*256 + b*256 + ((k1 >> 16) & 255u)], 1u);
        if ((k2 >> 24) == hi) atomicAdd(&g_hist[1*BB*256 + b*256 + ((k2 >> 16) & 255u)], 1u);
        if ((k3 >> 24) == hi) atomicAdd(&g_hist[1*BB*256 + b*256 + ((k3 >> 16) & 255u)], 1u);
    }
}

// collect candidates at the 16-bit prefix (skips the former hist3 pass)
__global__ void collect_kernel() {
    __shared__ unsigned sh[258];
    int b = blockIdx.y;
    unsigned hi, need;
    compute_sel(b, 2, sh, hi, need);              // 16-bit prefix
    int base = blockIdx.x * (NNE/64);
    for (int it = 0; it < 4; it++) {
        int i4 = base + (threadIdx.x + 256*it) * 4;   // flat idx within batch
        float4 w = *(const float4*)&g_W[b*NNE + i4];
        unsigned k[4] = { ford(w.x), ford(w.y), ford(w.z), ford(w.w) };
#pragma unroll
        for (int j = 0; j < 4; j++) {
            if ((k[j] >> 16) == hi) {
                unsigned int pos = atomicAdd(&g_cnt[b], 1u);
                if (pos < CAP2)
                    g_cand[b*CAP2 + pos] =
                        ((unsigned long long)k[j] << 32) | (unsigned int)(i4 + j);
            }
        }
    }
}

// in-block byte-3 refinement over the candidate set, then exact rank
__global__ void select_kernel() {
    __shared__ unsigned long long s[CAP];
    __shared__ unsigned sh[258];
    __shared__ unsigned hcnt[256];
    __shared__ unsigned scnt;
    int b = blockIdx.x, t = threadIdx.x;
    unsigned hi, need;
    compute_sel(b, 2, sh, hi, need);              // 16-bit prefix + remaining need
    unsigned cnt = g_cnt[b]; if (cnt > CAP2) cnt = CAP2;

    hcnt[t] = 0u;
    if (t == 0) scnt = 0u;
    __syncthreads();
    // byte-3 histogram over candidates
    for (unsigned i = t; i < cnt; i += 256) {
        unsigned key = (unsigned)(g_cand[b*CAP2 + i] >> 32);
        atomicAdd(&hcnt[(key >> 8) & 255u], 1u);
    }
    __syncthreads();
    // suffix scan of hcnt
    sh[t] = hcnt[t];
    __syncthreads();
    for (int off = 1; off < 256; off <<= 1) {
        unsigned add = (t + off < 256) ? sh[t + off] : 0u;
        __syncthreads();
        sh[t] += add;
        __syncthreads();
    }
    {
        unsigned S     = sh[t];
        unsigned Snext = (t < 255) ? sh[t + 1] : 0u;
        __syncthreads();
        if (S >= need && Snext < need) { sh[256] = (unsigned)t; sh[257] = need - Snext; }
        __syncthreads();
    }
    unsigned b3 = sh[256], need2 = sh[257];
    __syncthreads();
    // gather candidates with byte-3 == b3 into smem
    for (unsigned i = t; i < cnt; i += 256) {
        unsigned long long kk = g_cand[b*CAP2 + i];
        unsigned key = (unsigned)(kk >> 32);
        if (((key >> 8) & 255u) == b3) {
            unsigned p = atomicAdd(&scnt, 1u);
            if (p < CAP) s[p] = kk;
        }
    }
    __syncthreads();
    unsigned fc = scnt; if (fc > CAP) fc = CAP;
    for (unsigned i = t; i < fc; i += 256) {
        unsigned long long k = s[i];
        unsigned greater = 0;
        for (unsigned j = 0; j < fc; j++) greater += (s[j] > k);
        if (greater == need2 - 1) g_cut[b] = k;   // keys unique: exactly one hit
    }
}

__global__ void mask_kernel(float* __restrict__ out) {
    int i4 = (blockIdx.x * blockDim.x + threadIdx.x) * 4;
    if (i4 >= BB*NNE) return;
    int b = i4 >> 18;                          // NNE = 2^18
    unsigned long long cut = g_cut[b];
    float4 w = *(const float4*)&g_W[i4];
    unsigned base = (unsigned)(i4 & (NNE - 1));
    float4 o;
    o.x = ((((unsigned long long)ford(w.x) << 32) | (base + 0u)) >= cut) ? 1.0f : 0.0f;
    o.y = ((((unsigned long long)ford(w.y) << 32) | (base + 1u)) >= cut) ? 1.0f : 0.0f;
    o.z = ((((unsigned long long)ford(w.z) << 32) | (base + 2u)) >= cut) ? 1.0f : 0.0f;
    o.w = ((((unsigned long long)ford(w.w) << 32) | (base + 3u)) >= cut) ? 1.0f : 0.0f;
    *(float4*)&out[i4] = o;
}

// ---------------- launch ----------------------------------------------------
extern "C" void kernel_launch(void* const* d_in, const int* in_sizes, int n_in,
                              void* d_out, int out_size) {
    const float* x = (const float*)d_in[0];
    float* out = (float*)d_out;
    (void)in_sizes; (void)n_in; (void)out_size;

    stats_kernel<<<BB*NLEN/8, 256>>>(x);
    ecv_kernel<<<dim3(36, BB), 512>>>(x);
    gemm_nt_kernel<<<dim3(4, 4, BB), 256>>>();
    softmax_kernel<<<BB*NLEN, 128>>>();
    gemm_nn_kernel<<<dim3(4, 4, BB), 256>>>();
    hist2_kernel<<<dim3(64, BB), 256>>>();
    collect_kernel<<<dim3(64, BB), 256>>>();
    select_kernel<<<BB, 256>>>();
    mask_kernel<<<(BB*NNE/4 + 255)/256, 256>>>(out);
}